// round 17
// baseline (speedup 1.0000x reference)
#include <cuda_runtime.h>
#include <cuda_fp16.h>
#include <cstdint>

#define BB 2
#define SS 2048
#define DIN 1024
#define DM 1024
#define HH 16
#define HD 64
#define BH (BB*HH)

// ---------------------------------------------------------------------------
// Scratch (__device__ globals; no allocation allowed)
// ---------------------------------------------------------------------------
__device__ uint32_t g_qhp[BH*SS*HD/2];       // Q fp16 hi, pre-scaled, [bh][s][d_word]
__device__ uint32_t g_khp[BH*SS*HD/2];       // K fp16 hi
__device__ uint32_t g_vhp[BH*SS*HD/2];       // V fp16 hi
__device__ uint32_t g_xhp[BB*SS*DIN/2];      // x fp16 [M][K/2] hi words
__device__ uint32_t g_wqhp[3*DM*(DIN/2)];    // W_qkv^T fp16 [N][K/2] hi
__device__ uint32_t g_wohp[DM*(DM/2)];       // W_out^T fp16 [N][K/2] hi
__device__ uint32_t g_athp[BB*SS*DM/2];      // attn out fp16 hi

// ---------------------------------------------------------------------------
// fp16 helpers
// ---------------------------------------------------------------------------
__device__ __forceinline__ uint32_t pk2h(float a, float b) {
    __half2 v = __floats2half2_rn(a, b);
    return *reinterpret_cast<uint32_t*>(&v);
}
__device__ __forceinline__ float hhi(float a) {
    return __half2float(__float2half_rn(a));
}
__device__ __forceinline__ uint32_t h2exp2_pk(float a, float b) {
    uint32_t tp = pk2h(a, b);
    uint32_t r;
    asm("ex2.approx.f16x2 %0, %1;" : "=r"(r) : "r"(tp));
    return r;
}

__device__ __forceinline__ void mma_f16(float c[4],
                                        uint32_t a0, uint32_t a1, uint32_t a2, uint32_t a3,
                                        uint32_t b0, uint32_t b1) {
    asm volatile(
        "mma.sync.aligned.m16n8k16.row.col.f32.f16.f16.f32 "
        "{%0,%1,%2,%3}, {%4,%5,%6,%7}, {%8,%9}, {%0,%1,%2,%3};"
        : "+f"(c[0]), "+f"(c[1]), "+f"(c[2]), "+f"(c[3])
        : "r"(a0), "r"(a1), "r"(a2), "r"(a3), "r"(b0), "r"(b1));
}

__device__ __forceinline__ void cp16(uint32_t dst, const void* src) {
    asm volatile("cp.async.ca.shared.global [%0], [%1], 16;" :: "r"(dst), "l"(src));
}
__device__ __forceinline__ void cp_commit() { asm volatile("cp.async.commit_group;"); }
template <int n>
__device__ __forceinline__ void cp_wait() { asm volatile("cp.async.wait_group %0;" :: "n"(n)); }

#define LDSM4(r, addr) \
    asm volatile("ldmatrix.sync.aligned.m8n8.x4.shared.b16 {%0,%1,%2,%3}, [%4];" \
                 : "=r"((r)[0]), "=r"((r)[1]), "=r"((r)[2]), "=r"((r)[3]) \
                 : "r"(addr))
#define LDSM4T(r, addr) \
    asm volatile("ldmatrix.sync.aligned.m8n8.x4.trans.shared.b16 {%0,%1,%2,%3}, [%4];" \
                 : "=r"((r)[0]), "=r"((r)[1]), "=r"((r)[2]), "=r"((r)[3]) \
                 : "r"(addr))

// ---------------------------------------------------------------------------
// Merged pack kernel
// ---------------------------------------------------------------------------
#define DEC_NA (BB*SS*DIN/8)
#define DEC_NB (3*DM*(DIN/8))
#define DEC_NC (DM*(DM/8))

__global__ void dec_all_kernel(const float* __restrict__ x, uint32_t* __restrict__ xhp,
                               const float* __restrict__ wq, uint32_t* __restrict__ wqhp,
                               const float* __restrict__ wo, uint32_t* __restrict__ wohp) {
    int i = blockIdx.x * blockDim.x + threadIdx.x;
    if (i < DEC_NA) {
        const float4* s4 = (const float4*)x;
        float4 v0 = s4[2 * i], v1 = s4[2 * i + 1];
        uint4 h;
        h.x = pk2h(hhi(v0.x), hhi(v0.y));
        h.y = pk2h(hhi(v0.z), hhi(v0.w));
        h.z = pk2h(hhi(v1.x), hhi(v1.y));
        h.w = pk2h(hhi(v1.z), hhi(v1.w));
        ((uint4*)xhp)[i] = h;
    } else if (i < DEC_NA + DEC_NB) {
        int j = i - DEC_NA;
        const int N = 3 * DM;
        int kc = j / N;
        int n = j % N;
        float v[8];
#pragma unroll
        for (int q = 0; q < 8; q++) v[q] = wq[(size_t)(kc * 8 + q) * N + n];
        uint4 h;
        h.x = pk2h(hhi(v[0]), hhi(v[1]));
        h.y = pk2h(hhi(v[2]), hhi(v[3]));
        h.z = pk2h(hhi(v[4]), hhi(v[5]));
        h.w = pk2h(hhi(v[6]), hhi(v[7]));
        *(uint4*)(wqhp + (size_t)n * (DIN / 2) + kc * 4) = h;
    } else if (i < DEC_NA + DEC_NB + DEC_NC) {
        int j = i - DEC_NA - DEC_NB;
        const int N = DM;
        int kc = j / N;
        int n = j % N;
        float v[8];
#pragma unroll
        for (int q = 0; q < 8; q++) v[q] = wo[(size_t)(kc * 8 + q) * N + n];
        uint4 h;
        h.x = pk2h(hhi(v[0]), hhi(v[1]));
        h.y = pk2h(hhi(v[2]), hhi(v[3]));
        h.z = pk2h(hhi(v[4]), hhi(v[5]));
        h.w = pk2h(hhi(v[6]), hhi(v[7]));
        *(uint4*)(wohp + (size_t)n * (DM / 2) + kc * 4) = h;
    }
}

// ---------------------------------------------------------------------------
// 1-term fp16 GEMM with ldmatrix. CTA 128x128, k-tile 64 elems (32 words).
// 8 warps 2m x 4n, warp 64x32. 3-stage cp.async, ONE barrier per k-tile.
// ---------------------------------------------------------------------------
#define GPAD 36
#define GTILE (128 * GPAD)                // 4608 words per operand tile
#define GSTG2 (2 * GTILE)                 // A hi + B hi per stage
#define GEMM_SMEM_BYTES (3 * GSTG2 * 4)   // 110592

template <int N, bool SCATTER>
__global__ void __launch_bounds__(256, 2) f16_gemm_hi(const uint32_t* __restrict__ Ahp,
                                                      const uint32_t* __restrict__ Bhp,
                                                      const float* __restrict__ bias,
                                                      float* __restrict__ out) {
    constexpr int KW = 512;
    constexpr int KT = 16;     // k-tiles of 64 elems (32 words)
    extern __shared__ uint32_t smw[];
    const int tid = threadIdx.x;
    const int lane = tid & 31;
    const int warp = tid >> 5;
    const int wm = warp & 1;
    const int wn = warp >> 1;
    const int g = lane >> 2;
    const int t = lane & 3;
    const int mBase = blockIdx.y * 128;
    const int nBase = blockIdx.x * 128;

    const int fRow = tid >> 1;
    const int fh = (tid & 1) * 16;
    const uint32_t* gAh = Ahp + (size_t)(mBase + fRow) * KW + fh;
    const uint32_t* gBh = Bhp + (size_t)(nBase + fRow) * KW + fh;

    const uint32_t sBase = (uint32_t)__cvta_generic_to_shared(smw);
    const uint32_t fOff = (fRow * GPAD + fh) * 4;

    auto loadStage = [&](int s, int kt) {
        uint32_t b0 = sBase + s * (GSTG2 * 4);
        int kw = kt * 32;
#pragma unroll
        for (int c2 = 0; c2 < 4; c2++) {
            cp16(b0 + fOff + c2 * 16, gAh + kw + c2 * 4);
            cp16(b0 + GTILE * 4 + fOff + c2 * 16, gBh + kw + c2 * 4);
        }
    };

    const int aOff = ((lane & 7) + ((lane >> 3) & 1) * 8) * GPAD + ((lane >> 4) & 1) * 4;
    const int bOff = ((lane & 7) + ((lane >> 4) & 1) * 8) * GPAD + ((lane >> 3) & 1) * 4;

    float c[4][4][4];
#pragma unroll
    for (int mi = 0; mi < 4; mi++)
#pragma unroll
        for (int ni = 0; ni < 4; ni++)
#pragma unroll
            for (int r = 0; r < 4; r++) c[mi][ni][r] = 0.f;

    loadStage(0, 0);
    cp_commit();
    loadStage(1, 1);
    cp_commit();

    for (int kt = 0; kt < KT; kt++) {
        if (kt + 1 < KT) cp_wait<1>();
        else cp_wait<0>();
        __syncthreads();

        if (kt + 2 < KT) {
            loadStage((kt + 2) % 3, kt + 2);
            cp_commit();
        }

        const uint32_t sb = sBase + (kt % 3) * (GSTG2 * 4);
        const uint32_t sAh_u = sb;
        const uint32_t sBh_u = sb + GTILE * 4;

#pragma unroll
        for (int ks = 0; ks < 4; ks++) {
            const int kw0 = ks * 8;
            uint32_t ah[4][4], bh[2][4];
#pragma unroll
            for (int mi = 0; mi < 4; mi++) {
                uint32_t base = ((wm * 64 + mi * 16) * GPAD + aOff + kw0) * 4;
                LDSM4(ah[mi], sAh_u + base);
            }
#pragma unroll
            for (int q = 0; q < 2; q++) {
                uint32_t base = ((wn * 32 + q * 16) * GPAD + bOff + kw0) * 4;
                LDSM4(bh[q], sBh_u + base);
            }
#pragma unroll
            for (int mi = 0; mi < 4; mi++)
#pragma unroll
                for (int ni = 0; ni < 4; ni++) {
                    const int q = ni >> 1;
                    const int r = (ni & 1) * 2;
                    mma_f16(c[mi][ni], ah[mi][0], ah[mi][1], ah[mi][2], ah[mi][3],
                            bh[q][r], bh[q][r + 1]);
                }
        }
    }

    // Epilogue
#pragma unroll
    for (int mi = 0; mi < 4; mi++) {
#pragma unroll
        for (int ni = 0; ni < 4; ni++) {
#pragma unroll
            for (int half = 0; half < 2; half++) {
                int m = mBase + wm * 64 + mi * 16 + g + half * 8;
                int n = nBase + wn * 32 + ni * 8 + t * 2;
                float v0 = c[mi][ni][half * 2 + 0] + bias[n];
                float v1 = c[mi][ni][half * 2 + 1] + bias[n + 1];
                if (SCATTER) {
                    int b = m >> 11;
                    int s2 = m & (SS - 1);
                    int h = n / 192;
                    int rem = n - h * 192;
                    int ty2 = rem >> 6;
                    int d = rem & 63;
                    size_t widx = ((size_t)(b * HH + h) * SS + s2) * (HD / 2) + (d >> 1);
                    if (ty2 == 0) {
                        g_qhp[widx] = pk2h(v0 * 0.125f, v1 * 0.125f);
                    } else if (ty2 == 1) {
                        g_khp[widx] = pk2h(hhi(v0), hhi(v1));
                    } else {
                        g_vhp[widx] = pk2h(hhi(v0), hhi(v1));
                    }
                } else {
                    *(float2*)(out + (size_t)m * N + n) = make_float2(v0, v1);
                }
            }
        }
    }
}

// ---------------------------------------------------------------------------
// fp16 flash attention: 1-term QK^T, 1-term P@V, h2exp softmax, ones-col sum.
// Q tile 128, KV tile 64, 8 warps x 16 exclusive rows, 2 CTAs/SM.
// ---------------------------------------------------------------------------
#define AQP 36
#define AQSZ (128 * AQP)
#define AKSZ (64 * AQP)
#define ASTG (2 * AKSZ)
#define ATTN_SMEM_WORDS (2 * AQSZ + 3 * ASTG)
#define ATTN_SMEM_BYTES (ATTN_SMEM_WORDS * 4)   // 92160
#define ONES_H2 0x3C003C00u
#define L2E 1.4426950408889634f

__global__ void __launch_bounds__(256, 2) attn_kernel10() {
    extern __shared__ uint32_t smw[];
    uint32_t* sPh = smw + AQSZ;

    const int tid = threadIdx.x;
    const int lane = tid & 31;
    const int warp = tid >> 5;
    const int g = lane >> 2;
    const int t = lane & 3;
    const int qt = (gridDim.x - 1) - blockIdx.x;
    const int bh = blockIdx.y;
    const int b = bh >> 4, h = bh & 15;
    const int qBase = qt * 128;
    const int m0 = warp * 16;

    const uint32_t* Qh = g_qhp + (size_t)(bh * SS + qBase) * (HD / 2);
    const uint32_t* Kh = g_khp + (size_t)bh * SS * (HD / 2);
    const uint32_t* Vh = g_vhp + (size_t)bh * SS * (HD / 2);

    const uint32_t sBase = (uint32_t)__cvta_generic_to_shared(smw);
    const uint32_t sQh_u = sBase;
    const uint32_t sPh_u = sBase + AQSZ * 4;
    const uint32_t sRing_u = sBase + 2 * AQSZ * 4;

    const int aOff = ((lane & 7) + ((lane >> 3) & 1) * 8) * AQP + ((lane >> 4) & 1) * 4;
    const int bOff = ((lane & 7) + ((lane >> 4) & 1) * 8) * AQP + ((lane >> 3) & 1) * 4;
    const int vOff = ((lane & 7) + ((lane >> 3) & 1) * 8) * AQP + ((lane >> 4) & 1) * 4;

    // Q load: 128 rows x 32 words, 2 threads/row
    {
        int qRow = tid >> 1;
        int qc = (tid & 1) * 16;
        const uint32_t* gh = Qh + (size_t)qRow * 32 + qc;
        uint32_t dst = (qRow * AQP + qc) * 4;
#pragma unroll
        for (int c2 = 0; c2 < 4; c2++) cp16(sQh_u + dst + c2 * 16, gh + c2 * 4);
    }

    const int kRow = tid >> 2;
    const int kc = (tid & 3) * 8;
    auto prefetchKV = [&](int stg, int j) {
        int kvB = j * 64;
        uint32_t dst = sRing_u + (stg * ASTG + kRow * AQP + kc) * 4;
        const uint32_t* gk = Kh + (size_t)(kvB + kRow) * 32 + kc;
        const uint32_t* gv = Vh + (size_t)(kvB + kRow) * 32 + kc;
        cp16(dst, gk);
        cp16(dst + 16, gk + 4);
        cp16(dst + AKSZ * 4, gv);
        cp16(dst + AKSZ * 4 + 16, gv + 4);
    };

    float m_[2] = {-1e30f, -1e30f};
    float co[8][4];
    float lsum[4];   // ones-column accumulator: [0],[1] row g; [2],[3] row g+8
#pragma unroll
    for (int ni = 0; ni < 8; ni++)
#pragma unroll
        for (int r = 0; r < 4; r++) co[ni][r] = 0.f;
#pragma unroll
    for (int r = 0; r < 4; r++) lsum[r] = 0.f;

    const int jmax = 2 * qt + 1;
    prefetchKV(0, 0);
    cp_commit();
    prefetchKV(1, 1);
    cp_commit();

    for (int j = 0; j <= jmax; j++) {
        const int kvBase = j * 64;
        const int stg = j % 3;
        if (j < jmax) cp_wait<1>();
        else cp_wait<0>();
        __syncthreads();

        if (j + 2 <= jmax) {
            prefetchKV((j + 2) % 3, j + 2);
            cp_commit();
        }

        if (kvBase > qBase + m0 + 15) continue;

        const uint32_t sK_u = sRing_u + stg * ASTG * 4;
        const uint32_t sV_u = sK_u + AKSZ * 4;

        // Scores S = Q K^T (1-term fp16)
        float sc[8][4];
#pragma unroll
        for (int ni = 0; ni < 8; ni++)
#pragma unroll
            for (int r = 0; r < 4; r++) sc[ni][r] = 0.f;
#pragma unroll
        for (int ks = 0; ks < 4; ks++) {
            const int kw0 = ks * 8;
            uint32_t qh[4], kb[4][4];
            uint32_t abase = (m0 * AQP + aOff + kw0) * 4;
            LDSM4(qh, sQh_u + abase);
#pragma unroll
            for (int q2 = 0; q2 < 4; q2++) {
                uint32_t bbase = ((q2 * 16) * AQP + bOff + kw0) * 4;
                LDSM4(kb[q2], sK_u + bbase);
            }
#pragma unroll
            for (int ni = 0; ni < 8; ni++) {
                const int q2 = ni >> 1;
                const int r = (ni & 1) * 2;
                mma_f16(sc[ni], qh[0], qh[1], qh[2], qh[3], kb[q2][r], kb[q2][r + 1]);
            }
        }

        // Causal mask
        if (kvBase + 63 > qBase + m0) {
#pragma unroll
            for (int ni = 0; ni < 8; ni++) {
#pragma unroll
                for (int r = 0; r < 4; r++) {
                    int row = qBase + m0 + g + ((r >= 2) ? 8 : 0);
                    int col = kvBase + ni * 8 + 2 * t + (r & 1);
                    if (col > row) sc[ni][r] = -1e30f;
                }
            }
        }

        // Warp-local online softmax (rows g and g+8); sums via ones-column mma
        float mx0 = -1e30f, mx1 = -1e30f;
#pragma unroll
        for (int ni = 0; ni < 8; ni++) {
            mx0 = fmaxf(mx0, fmaxf(sc[ni][0], sc[ni][1]));
            mx1 = fmaxf(mx1, fmaxf(sc[ni][2], sc[ni][3]));
        }
#pragma unroll
        for (int o = 1; o <= 2; o <<= 1) {
            mx0 = fmaxf(mx0, __shfl_xor_sync(0xffffffffu, mx0, o));
            mx1 = fmaxf(mx1, __shfl_xor_sync(0xffffffffu, mx1, o));
        }
        float mn0 = fmaxf(m_[0], mx0), mn1 = fmaxf(m_[1], mx1);
        float a0 = __expf(m_[0] - mn0), a1 = __expf(m_[1] - mn1);
        m_[0] = mn0; m_[1] = mn1;
        float mnL0 = mn0 * L2E, mnL1 = mn1 * L2E;
#pragma unroll
        for (int ni = 0; ni < 8; ni++) {
            co[ni][0] *= a0; co[ni][1] *= a0;
            co[ni][2] *= a1; co[ni][3] *= a1;
        }
        lsum[0] *= a0; lsum[1] *= a0;
        lsum[2] *= a1; lsum[3] *= a1;

        // P = exp2(s*log2e - m*log2e), packed fp16x2 straight from MUFU
#pragma unroll
        for (int ni = 0; ni < 8; ni++) {
            int w0 = (m0 + g) * AQP + ni * 4 + t;
            int w1 = (m0 + g + 8) * AQP + ni * 4 + t;
            sPh[w0] = h2exp2_pk(fmaf(sc[ni][0], L2E, -mnL0), fmaf(sc[ni][1], L2E, -mnL0));
            sPh[w1] = h2exp2_pk(fmaf(sc[ni][2], L2E, -mnL1), fmaf(sc[ni][3], L2E, -mnL1));
        }
        __syncwarp();

        // O += P @ V, l += P @ ones (1-term fp16)
#pragma unroll
        for (int ks = 0; ks < 4; ks++) {
            const int kw0 = ks * 8;
            uint32_t ph[4];
            uint32_t abase = (m0 * AQP + aOff + kw0) * 4;
            LDSM4(ph, sPh_u + abase);
#pragma unroll
            for (int np = 0; np < 4; np++) {
                uint32_t vb[4];
                uint32_t vbase = ((ks * 16) * AQP + np * 8 + vOff) * 4;
                LDSM4T(vb, sV_u + vbase);
                mma_f16(co[2 * np], ph[0], ph[1], ph[2], ph[3], vb[0], vb[1]);
                mma_f16(co[2 * np + 1], ph[0], ph[1], ph[2], ph[3], vb[2], vb[3]);
            }
            mma_f16(lsum, ph[0], ph[1], ph[2], ph[3], ONES_H2, ONES_H2);
        }
    }

    // Epilogue: normalize (lsum cols identical per row), pack fp16 hi
    float inv0 = 1.0f / lsum[0];
    float inv1 = 1.0f / lsum[2];
    int r0 = qBase + m0 + g;
    int r1 = r0 + 8;
#pragma unroll
    for (int ni = 0; ni < 8; ni++) {
        int w = h * (HD / 2) + ni * 4 + t;
        size_t i0 = (size_t)(b * SS + r0) * (DM / 2) + w;
        size_t i1 = (size_t)(b * SS + r1) * (DM / 2) + w;
        g_athp[i0] = pk2h(co[ni][0] * inv0, co[ni][1] * inv0);
        g_athp[i1] = pk2h(co[ni][2] * inv1, co[ni][3] * inv1);
    }
}

// ---------------------------------------------------------------------------

extern "C" void kernel_launch(void* const* d_in, const int* in_sizes, int n_in,
                              void* d_out, int out_size) {
    (void)in_sizes; (void)n_in; (void)out_size;
    const float* x     = (const float*)d_in[0];
    const float* w_qkv = (const float*)d_in[1];
    const float* b_qkv = (const float*)d_in[2];
    const float* w_out = (const float*)d_in[3];
    const float* b_out = (const float*)d_in[4];
    float* out = (float*)d_out;

    uint32_t *xhp, *wqhp, *wohp, *athp;
    cudaGetSymbolAddress((void**)&xhp, g_xhp);
    cudaGetSymbolAddress((void**)&wqhp, g_wqhp);
    cudaGetSymbolAddress((void**)&wohp, g_wohp);
    cudaGetSymbolAddress((void**)&athp, g_athp);

    // Pack x + both weight transposes in one launch
    {
        int total = DEC_NA + DEC_NB + DEC_NC;
        dec_all_kernel<<<(total + 255) / 256, 256>>>(x, xhp, w_qkv, wqhp, w_out, wohp);
    }

    // QKV GEMM (scatter packed fp16 q/k/v)
    {
        cudaFuncSetAttribute(f16_gemm_hi<3 * DM, true>,
                             cudaFuncAttributeMaxDynamicSharedMemorySize, GEMM_SMEM_BYTES);
        dim3 grid(3 * DM / 128, BB * SS / 128);
        f16_gemm_hi<3 * DM, true><<<grid, 256, GEMM_SMEM_BYTES>>>(xhp, wqhp, b_qkv, nullptr);
    }
    // Flash attention
    {
        cudaFuncSetAttribute(attn_kernel10, cudaFuncAttributeMaxDynamicSharedMemorySize, ATTN_SMEM_BYTES);
        dim3 grid(SS / 128, BH);
        attn_kernel10<<<grid, 256, ATTN_SMEM_BYTES>>>();
    }
    // Output GEMM
    {
        cudaFuncSetAttribute(f16_gemm_hi<DM, false>,
                             cudaFuncAttributeMaxDynamicSharedMemorySize, GEMM_SMEM_BYTES);
        dim3 grid(DM / 128, BB * SS / 128);
        f16_gemm_hi<DM, false><<<grid, 256, GEMM_SMEM_BYTES>>>(athp, wohp, b_out, out);
    }
}